// round 6
// baseline (speedup 1.0000x reference)
#include <cuda_runtime.h>
#include <cuda_fp16.h>
#include <cstdint>
#include <cstddef>

// Problem dims
#define NB 32
#define NS 2048
#define NH 1024
#define NE 2048              // 2*H
#define NR (NB*NS)           // 65536 rows

// ---------------- device scratch (static, no runtime allocs) ----------------
__device__ __half g_enc_h[(size_t)NR * NE]; // 268 MB: enc converted to fp16
__device__ __half g_Wk_h[NH * NE];          // 4 MB: Wk fp16 (K-major [h][e])
__device__ float  g_query[NB * NH];         // query[b][h]
__device__ float  g_spart[4 * NR];          // partial scores per n-block (4 blocks of 256)
__device__ float  g_alphas[NR];             // softmax result
__device__ float  g_cpart[8 * NB * NE];     // context partials (s-split by 8)

// ---------------- helpers (baseline PTX only: sm_80-era instructions) -------
__device__ __forceinline__ uint32_t smem_u32(const void* p) {
    uint32_t a;
    asm("{ .reg .u64 t; cvta.to.shared.u64 t, %1; cvt.u32.u64 %0, t; }" : "=r"(a) : "l"(p));
    return a;
}
__device__ __forceinline__ void cp16(uint32_t s, const void* g) {
    asm volatile("cp.async.cg.shared.global [%0], [%1], 16;" :: "r"(s), "l"(g));
}
#define CP_COMMIT() asm volatile("cp.async.commit_group;" ::: "memory")
#define CP_WAIT(n)  asm volatile("cp.async.wait_group %0;" :: "n"(n) : "memory")

__device__ __forceinline__ void ldsm4(uint32_t* r, uint32_t addr) {
    asm volatile("ldmatrix.sync.aligned.m8n8.x4.shared.b16 {%0,%1,%2,%3}, [%4];"
        : "=r"(r[0]), "=r"(r[1]), "=r"(r[2]), "=r"(r[3]) : "r"(addr));
}
__device__ __forceinline__ void mma16816(float* c, const uint32_t* a, uint32_t b0, uint32_t b1) {
    asm volatile("mma.sync.aligned.m16n8k16.row.col.f32.f16.f16.f32 "
        "{%0,%1,%2,%3}, {%4,%5,%6,%7}, {%8,%9}, {%0,%1,%2,%3};"
        : "+f"(c[0]), "+f"(c[1]), "+f"(c[2]), "+f"(c[3])
        : "r"(a[0]), "r"(a[1]), "r"(a[2]), "r"(a[3]), "r"(b0), "r"(b1));
}

// SW128 swizzle for 128B rows (conflict-free ldmatrix + cp.async stores)
#define SW128(o) ((o) ^ (((o) >> 3) & 0x70))

// ---------------- smem layout for scores kernel ----------------
// 3 pipeline stages, each: A tile 128x64 fp16 (16 KB) + B tile 256x64 fp16 (32 KB)
#define STAGE_BYTES 49152
#define ST_A(i)     ((i) * STAGE_BYTES)
#define ST_B(i)     ((i) * STAGE_BYTES + 16384)
#define OFF_Q       147456                    // 256 floats
#define OFF_WE      148480                    // 256 floats
#define OFF_RED     149504                    // 512 floats
#define SMEM_TOTAL  151552                    // 148 KB

#define KT      64
#define NSTEPS  (NE / KT)                     // 32

// ---------------- prep kernels ----------------
__global__ void enc_convert_kernel(const float* __restrict__ enc) {
    size_t i = (size_t)blockIdx.x * blockDim.x + threadIdx.x;  // over NR*NE/4
    if (i < ((size_t)NR * NE) / 4) {
        float4 f = ((const float4*)enc)[i];
        __half2 a = __floats2half2_rn(f.x, f.y);
        __half2 b = __floats2half2_rn(f.z, f.w);
        ((__half2*)g_enc_h)[2 * i]     = a;
        ((__half2*)g_enc_h)[2 * i + 1] = b;
    }
}
__global__ void wk_convert_kernel(const float* __restrict__ Wk) {
    int i = blockIdx.x * blockDim.x + threadIdx.x;             // over NH*NE/4
    if (i < (NH * NE) / 4) {
        float4 f = ((const float4*)Wk)[i];
        __half2 a = __floats2half2_rn(f.x, f.y);
        __half2 b = __floats2half2_rn(f.z, f.w);
        ((__half2*)g_Wk_h)[2 * i]     = a;
        ((__half2*)g_Wk_h)[2 * i + 1] = b;
    }
}

__global__ void __launch_bounds__(128) query_kernel(const float* __restrict__ dec,
                                                    const float* __restrict__ Wq) {
    __shared__ float ds[NH];
    int b = blockIdx.y, hc = blockIdx.x, tid = threadIdx.x;
    for (int i = tid; i < NH; i += 128) ds[i] = dec[b * NH + i];
    __syncthreads();
    int h = hc * 128 + tid;
    const float* wr = Wq + (size_t)h * NH;
    float a0 = 0, a1 = 0, a2 = 0, a3 = 0;
    for (int e = 0; e < NH; e += 4) {
        a0 += wr[e + 0] * ds[e + 0];
        a1 += wr[e + 1] * ds[e + 1];
        a2 += wr[e + 2] * ds[e + 2];
        a3 += wr[e + 3] * ds[e + 3];
    }
    g_query[b * NH + h] = (a0 + a1) + (a2 + a3);
}

// ---------------- fused scores GEMM (mma.sync fp16, fused tanh/We epilogue) --
// CTA: 128 rows x 256 cols. 8 warps as 2(m) x 4(n); warp tile 64x64.
__device__ __forceinline__ void issue_loads(uint32_t sbase, int stage, int s,
                                            int m0, int nblk, int tid) {
    const __half* ga = g_enc_h + (size_t)m0 * NE + s * KT;
    const __half* gb = g_Wk_h + (size_t)(nblk * 256) * NE + s * KT;
    uint32_t sa = sbase + ST_A(stage);
    uint32_t sbuf = sbase + ST_B(stage);
#pragma unroll
    for (int t = 0; t < 4; ++t) {          // A: 128 rows x 4 chunks of 16B
        int id = tid + t * 256;
        int r = id >> 3, c = id & 7;
        cp16(sa + SW128(r * 128 + c * 16), ga + (size_t)r * NE + c * 8);
    }
#pragma unroll
    for (int t = 0; t < 8; ++t) {          // B: 256 rows x 8 chunks of 16B
        int id = tid + t * 256;
        int r = id >> 3, c = id & 7;
        cp16(sbuf + SW128(r * 128 + c * 16), gb + (size_t)r * NE + c * 8);
    }
}

__global__ void __launch_bounds__(256, 1) scores_kernel(const float* __restrict__ We) {
    extern __shared__ char smem[];
    const int tid = threadIdx.x;
    const int wid = tid >> 5;
    const int lid = tid & 31;
    const uint32_t sb = smem_u32(smem);
    const int nblk = blockIdx.x;           // 0..3 (fast dim -> A reuse in L2)
    const int m0 = blockIdx.y * 128;       // row block (within one batch b)
    const int b = m0 >> 11;
    const int wm = wid >> 2;               // 0..1
    const int wn = wid & 3;                // 0..3

    float* q_s  = (float*)(smem + OFF_Q);
    float* we_s = (float*)(smem + OFF_WE);
    {
        int h = nblk * 256 + tid;
        q_s[tid]  = g_query[b * NH + h];
        we_s[tid] = We[h];
    }

    // pipeline prologue: stages 0 and 1
    issue_loads(sb, 0, 0, m0, nblk, tid); CP_COMMIT();
    issue_loads(sb, 1, 1, m0, nblk, tid); CP_COMMIT();

    float acc[4][8][4];
#pragma unroll
    for (int mi = 0; mi < 4; ++mi)
#pragma unroll
        for (int nj = 0; nj < 8; ++nj)
#pragma unroll
            for (int k = 0; k < 4; ++k) acc[mi][nj][k] = 0.0f;

    const int lrow = lid & 15;
    const int lcol = (lid >> 4) * 16;

    int st_cur = 0;    // ring counters replace s%3 (no integer div in hot loop)
    int st_nxt = 2;
    for (int s = 0; s < NSTEPS; ++s) {
        if (s + 2 < NSTEPS) {
            issue_loads(sb, st_nxt, s + 2, m0, nblk, tid); CP_COMMIT();
            if (++st_nxt == 3) st_nxt = 0;
        }
        if (s + 2 < NSTEPS)      CP_WAIT(2);
        else if (s + 1 < NSTEPS) CP_WAIT(1);
        else                     CP_WAIT(0);
        __syncthreads();

        const uint32_t sa = sb + ST_A(st_cur);
        const uint32_t sbuf = sb + ST_B(st_cur);
        if (++st_cur == 3) st_cur = 0;
#pragma unroll
        for (int kb = 0; kb < 4; ++kb) {
            uint32_t af[4][4], bf[4][4];
#pragma unroll
            for (int mi = 0; mi < 4; ++mi)
                ldsm4(af[mi], sa + SW128((wm * 64 + mi * 16 + lrow) * 128 + kb * 32 + lcol));
#pragma unroll
            for (int nj2 = 0; nj2 < 4; ++nj2)
                ldsm4(bf[nj2], sbuf + SW128((wn * 64 + nj2 * 16 + lrow) * 128 + kb * 32 + lcol));
#pragma unroll
            for (int mi = 0; mi < 4; ++mi)
#pragma unroll
                for (int nj = 0; nj < 8; ++nj)
                    mma16816(acc[mi][nj], af[mi], bf[nj >> 1][nj & 1], bf[nj >> 1][(nj & 1) + 2]);
        }
        __syncthreads();
    }

    // ---- fused epilogue: tanh(d + q) * we, reduce over 256 cols ----
    float rl[4] = {0, 0, 0, 0}, rh[4] = {0, 0, 0, 0};
#pragma unroll
    for (int mi = 0; mi < 4; ++mi)
#pragma unroll
        for (int nj = 0; nj < 8; ++nj) {
            int col = wn * 64 + nj * 8 + 2 * (lid & 3);
            float q0 = q_s[col], q1 = q_s[col + 1];
            float w0 = we_s[col], w1 = we_s[col + 1];
            rl[mi] += tanhf(acc[mi][nj][0] + q0) * w0 + tanhf(acc[mi][nj][1] + q1) * w1;
            rh[mi] += tanhf(acc[mi][nj][2] + q0) * w0 + tanhf(acc[mi][nj][3] + q1) * w1;
        }
    // quad reduce (lanes 4r..4r+3 share row r)
#pragma unroll
    for (int mi = 0; mi < 4; ++mi) {
        rl[mi] += __shfl_xor_sync(0xFFFFFFFF, rl[mi], 1);
        rl[mi] += __shfl_xor_sync(0xFFFFFFFF, rl[mi], 2);
        rh[mi] += __shfl_xor_sync(0xFFFFFFFF, rh[mi], 1);
        rh[mi] += __shfl_xor_sync(0xFFFFFFFF, rh[mi], 2);
    }
    float* red = (float*)(smem + OFF_RED);   // [8 warps][64 rows]
    if ((lid & 3) == 0) {
        int r = lid >> 2;                    // 0..7
#pragma unroll
        for (int mi = 0; mi < 4; ++mi) {
            red[wid * 64 + mi * 16 + r]     = rl[mi];
            red[wid * 64 + mi * 16 + 8 + r] = rh[mi];
        }
    }
    __syncthreads();
    if (tid < 128) {
        int wmv = tid >> 6, rr = tid & 63;
        float sum = red[(wmv * 4 + 0) * 64 + rr] + red[(wmv * 4 + 1) * 64 + rr]
                  + red[(wmv * 4 + 2) * 64 + rr] + red[(wmv * 4 + 3) * 64 + rr];
        g_spart[nblk * NR + m0 + tid] = sum;
    }
}

// ---------------- softmax ----------------
__global__ void __launch_bounds__(256) softmax_kernel() {
    __shared__ float sc[NS];
    __shared__ float red[256];
    int b = blockIdx.x, tid = threadIdx.x;
    float mx = -1e30f;
    for (int s = tid; s < NS; s += 256) {
        float v = g_spart[b * NS + s] + g_spart[NR + b * NS + s]
                + g_spart[2 * NR + b * NS + s] + g_spart[3 * NR + b * NS + s];
        sc[s] = v;
        mx = fmaxf(mx, v);
    }
    red[tid] = mx; __syncthreads();
    for (int o = 128; o; o >>= 1) { if (tid < o) red[tid] = fmaxf(red[tid], red[tid + o]); __syncthreads(); }
    mx = red[0]; __syncthreads();
    float sm = 0.0f;
    for (int s = tid; s < NS; s += 256) {
        float e = expf(sc[s] - mx);
        sc[s] = e; sm += e;
    }
    red[tid] = sm; __syncthreads();
    for (int o = 128; o; o >>= 1) { if (tid < o) red[tid] += red[tid + o]; __syncthreads(); }
    float inv = 1.0f / red[0];
    for (int s = tid; s < NS; s += 256) g_alphas[b * NS + s] = sc[s] * inv;
}

// ---------------- context = alphas @ enc (fp32, memory-bound) ----------------
__global__ void __launch_bounds__(256) ctx_part_kernel(const float* __restrict__ enc) {
    __shared__ float al[256];
    int b = blockIdx.z, jc = blockIdx.x, sc = blockIdx.y, tid = threadIdx.x;
    al[tid] = g_alphas[b * NS + sc * 256 + tid];
    __syncthreads();
    int j = jc * 256 + tid;
    const float* ep = enc + ((size_t)b * NS + sc * 256) * NE + j;
    float acc = 0.0f;
#pragma unroll 8
    for (int s = 0; s < 256; ++s) acc += al[s] * ep[(size_t)s * NE];
    g_cpart[(size_t)sc * (NB * NE) + b * NE + j] = acc;
}

__global__ void __launch_bounds__(256) ctx_reduce_kernel(float* __restrict__ out) {
    int i = blockIdx.x * 256 + threadIdx.x;   // 0..65535
    float a = 0.0f;
#pragma unroll
    for (int sc = 0; sc < 8; ++sc) a += g_cpart[sc * (NB * NE) + i];
    out[i] = a;
}

// ---------------- launch ----------------
extern "C" void kernel_launch(void* const* d_in, const int* in_sizes, int n_in,
                              void* d_out, int out_size) {
    const float* enc = (const float*)d_in[0];
    const float* dec = (const float*)d_in[1];
    const float* Wq  = (const float*)d_in[2];
    const float* Wk  = (const float*)d_in[3];
    const float* We  = (const float*)d_in[4];
    float* out = (float*)d_out;

    cudaFuncSetAttribute(scores_kernel, cudaFuncAttributeMaxDynamicSharedMemorySize, SMEM_TOTAL);

    enc_convert_kernel<<<131072, 256>>>(enc);
    wk_convert_kernel<<<2048, 256>>>(Wk);
    query_kernel<<<dim3(8, 32), 128>>>(dec, Wq);
    scores_kernel<<<dim3(4, 512), 256, SMEM_TOTAL>>>(We);
    softmax_kernel<<<32, 256>>>();
    ctx_part_kernel<<<dim3(8, 8, 32), 256>>>(enc);
    ctx_reduce_kernel<<<256, 256>>>(out);
}